// round 3
// baseline (speedup 1.0000x reference)
#include <cuda_runtime.h>

#define PI_F     3.14159265358979323846f
#define FLOOR_Z  (-1.6f)

__device__ __forceinline__ float fast_sqrt(float x) {
    float r;
    asm("sqrt.approx.f32 %0, %1;" : "=f"(r) : "f"(x));
    return r;
}

// Computes one batch element entirely in registers.
// Inputs: bq0,bq1 = bottom_corners[b] (8 floats), tq0,tq1 = top_corners[b].
// Outputs: 3 float4 for top half and 3 float4 for bottom half.
__device__ __forceinline__ void process_one(
    float4 bq0, float4 bq1, float4 tq0, float4 tq1,
    float4& t0, float4& t1, float4& t2,
    float4& o0, float4& o1, float4& o2)
{
    float u[4]  = {bq0.x, bq0.z, bq1.x, bq1.z};
    float vv[4] = {bq0.y, bq0.w, bq1.y, bq1.w};
    float tv[4] = {tq0.y, tq0.w, tq1.y, tq1.w};

    // floor_xy ; cnorm = |c| exactly since px=c*sin, py=-c*cos
    float px[4], py[4];
    float czs = 0.f;
#pragma unroll
    for (int i = 0; i < 4; ++i) {
        float U = u[i] * PI_F;
        float V = vv[i] * (-0.5f * PI_F);
        float sv = __sinf(V), cv = __cosf(V);
        float c = __fdividef(FLOOR_Z * cv, sv);     // floor_z / tan(V)
        float s, co;
        __sincosf(U, &s, &co);
        px[i] = c * s;
        py[i] = -c * co;
        czs += fabsf(c) * __tanf(tv[i] * (-0.5f * PI_F));
    }
    float ceil_z = 0.25f * czs;
    float cx = 0.25f * (px[0] + px[1] + px[2] + px[3]);
    float cy = 0.25f * (py[0] + py[1] + py[2] + py[3]);

    // edge-length based scale: scale = [a_y, a_x] / 2
    float dx, dy;
    dx = px[0]-px[1]; dy = py[0]-py[1]; float ax1 = fast_sqrt(dx*dx + dy*dy);
    dx = px[1]-px[2]; dy = py[1]-py[2]; float ay1 = fast_sqrt(dx*dx + dy*dy);
    dx = px[2]-px[3]; dy = py[2]-py[3]; float ax2 = fast_sqrt(dx*dx + dy*dy);
    dx = px[3]-px[0]; dy = py[3]-py[0]; float ay2 = fast_sqrt(dx*dx + dy*dy);
    float sx = 0.25f * (ay1 + ay2);   // scale[...,0] = a_y/2 (multiplies x)
    float sy = 0.25f * (ax1 + ax2);   // scale[...,1] = a_x/2 (multiplies y)

    // centered floor points
    float fx[4], fy[4];
#pragma unroll
    for (int i = 0; i < 4; ++i) { fx[i] = px[i] - cx; fy[i] = py[i] - cy; }

    // Procrustes cross-covariance (sort-invariant); closed-form 2x2 Kabsch
    const float cubx[4] = {-1.f, -1.f,  1.f, 1.f};
    const float cuby[4] = { 1.f, -1.f, -1.f, 1.f};
    float Sxx = 0.f, Sxy = 0.f, Syx = 0.f, Syy = 0.f;
#pragma unroll
    for (int i = 0; i < 4; ++i) {
        Sxx += cubx[i] * fx[i];
        Sxy += cubx[i] * fy[i];
        Syx += cuby[i] * fx[i];
        Syy += cuby[i] * fy[i];
    }
    float rvar  = __fdividef(0.25f, sx*sx + sy*sy);
    float alpha = (sx * Sxx + sy * Syy) * rvar;   // scale_p * cos(theta)
    float beta  = (sx * Sxy - sy * Syx) * rvar;   // scale_p * sin(theta)

    // rectified points + pseudo-angle sort keys (monotonic with atan2(fx, fy+1e-12))
    float K[4], PX[4], PY[4];
#pragma unroll
    for (int i = 0; i < 4; ++i) {
        float wx = sx * cubx[i];
        float wy = sy * cuby[i];
        PX[i] = cx + alpha * wx - beta * wy;
        PY[i] = cy + beta  * wx + alpha * wy;
        float X = fx[i], Y = fy[i] + 1e-12f;
        float t = __fdividef(Y, fabsf(X) + fabsf(Y));
        K[i] = copysignf(1.f - t, X);
    }

    float K0=K[0],K1=K[1],K2=K[2],K3=K[3];
    float PX0=PX[0],PX1=PX[1],PX2=PX[2],PX3=PX[3];
    float PY0=PY[0],PY1=PY[1],PY2=PY[2],PY3=PY[3];
    float t_;
#define CSWAP(ka, kb, xa, xb, ya, yb)                                   \
    if (ka > kb) { t_=ka;ka=kb;kb=t_; t_=xa;xa=xb;xb=t_; t_=ya;ya=yb;yb=t_; }
    CSWAP(K0, K1, PX0, PX1, PY0, PY1)
    CSWAP(K2, K3, PX2, PX3, PY2, PY3)
    CSWAP(K0, K2, PX0, PX2, PY0, PY2)
    CSWAP(K1, K3, PX1, PX3, PY1, PY3)
    CSWAP(K1, K2, PX1, PX2, PY1, PY2)
#undef CSWAP

    t0 = make_float4(PX0, PY0, ceil_z, PX1);
    t1 = make_float4(PY1, ceil_z, PX2, PY2);
    t2 = make_float4(ceil_z, PX3, PY3, ceil_z);
    o0 = make_float4(PX0, PY0, FLOOR_Z, PX1);
    o1 = make_float4(PY1, FLOOR_Z, PX2, PY2);
    o2 = make_float4(FLOOR_Z, PX3, PY3, FLOOR_Z);
}

// 2 batch elements per thread: two independent dependency chains for ILP,
// contiguous 64B loads and 96B-per-half contiguous stores per thread.
__global__ void __launch_bounds__(256) cuboid_align_kernel(
    const float* __restrict__ top,   // [B,4,2]
    const float* __restrict__ bot,   // [B,4,2]
    float* __restrict__ out,         // [2,B,4,3]
    int B)
{
    int t = blockIdx.x * blockDim.x + threadIdx.x;
    int b0 = t * 2;
    if (b0 >= B) return;

    const float4* bp = (const float4*)bot + (size_t)b0 * 2;
    const float4* tp = (const float4*)top + (size_t)b0 * 2;

    // front-load all global reads (MLP = 8)
    float4 bA0 = bp[0], bA1 = bp[1], bB0 = bp[2], bB1 = bp[3];
    float4 tA0 = tp[0], tA1 = tp[1], tB0 = tp[2], tB1 = tp[3];

    float4 ta0, ta1, ta2, oa0, oa1, oa2;
    float4 tb0, tb1, tb2, ob0, ob1, ob2;
    process_one(bA0, bA1, tA0, tA1, ta0, ta1, ta2, oa0, oa1, oa2);
    process_one(bB0, bB1, tB0, tB1, tb0, tb1, tb2, ob0, ob1, ob2);

    float4* o_top = (float4*)(out + (size_t)b0 * 12);
    float4* o_bot = (float4*)(out + (size_t)B * 12 + (size_t)b0 * 12);
    o_top[0] = ta0; o_top[1] = ta1; o_top[2] = ta2;
    o_top[3] = tb0; o_top[4] = tb1; o_top[5] = tb2;
    o_bot[0] = oa0; o_bot[1] = oa1; o_bot[2] = oa2;
    o_bot[3] = ob0; o_bot[4] = ob1; o_bot[5] = ob2;
}

extern "C" void kernel_launch(void* const* d_in, const int* in_sizes, int n_in,
                              void* d_out, int out_size)
{
    const float* top = (const float*)d_in[0];  // top_corners    [B,4,2]
    const float* bot = (const float*)d_in[1];  // bottom_corners [B,4,2]
    // d_in[2] = cuboid_axes (constant [[-1,1],[-1,-1],[1,-1],[1,1]], hardcoded)
    int B = in_sizes[0] / 8;
    int nthreads_total = (B + 1) / 2;
    int threads = 256;
    int blocks = (nthreads_total + threads - 1) / threads;
    cuboid_align_kernel<<<blocks, threads>>>(top, bot, (float*)d_out, B);
}

// round 4
// speedup vs baseline: 1.2162x; 1.2162x over previous
#include <cuda_runtime.h>

#define PI_F     3.14159265358979323846f
#define FLOOR_Z  (-1.6f)

__device__ __forceinline__ float fast_sqrt(float x) {
    float r;
    asm("sqrt.approx.f32 %0, %1;" : "=f"(r) : "f"(x));
    return r;
}

// One thread per batch element. Closed-form pipeline:
//   * xf == axes exactly (homography applied to its own source points)
//   * closed-form 2x2 Kabsch (no SVD; sqrt cancels)
//   * sort-invariant Procrustes cross-covariance
//   * cnorm == |c| exactly (px=c sinU, py=-c cosU)
//   * pseudo-angle key + parallel rank-select permutation (no serial sort net)
__global__ void cuboid_align_kernel(
    const float* __restrict__ top,   // [B,4,2]
    const float* __restrict__ bot,   // [B,4,2]
    float* __restrict__ out,         // [2,B,4,3]
    int B)
{
    int b = blockIdx.x * blockDim.x + threadIdx.x;
    if (b >= B) return;

    const float4* bp = (const float4*)bot + (size_t)b * 2;
    const float4* tp = (const float4*)top + (size_t)b * 2;
    float4 bq0 = bp[0], bq1 = bp[1];
    float4 tq0 = tp[0], tq1 = tp[1];

    float u[4]  = {bq0.x, bq0.z, bq1.x, bq1.z};
    float vv[4] = {bq0.y, bq0.w, bq1.y, bq1.w};
    float tv[4] = {tq0.y, tq0.w, tq1.y, tq1.w};

    // floor_xy ; cnorm = |c| exactly
    float px[4], py[4];
    float czs = 0.f;
#pragma unroll
    for (int i = 0; i < 4; ++i) {
        float U = u[i] * PI_F;
        float V = vv[i] * (-0.5f * PI_F);
        float sv, cv;
        __sincosf(V, &sv, &cv);
        float c = __fdividef(FLOOR_Z * cv, sv);     // floor_z / tan(V)
        float s, co;
        __sincosf(U, &s, &co);
        px[i] = c * s;
        py[i] = -c * co;
        czs += fabsf(c) * __tanf(tv[i] * (-0.5f * PI_F));
    }
    float ceil_z = 0.25f * czs;
    float cx = 0.25f * (px[0] + px[1] + px[2] + px[3]);
    float cy = 0.25f * (py[0] + py[1] + py[2] + py[3]);

    // edge-length based scale: scale = [a_y, a_x] / 2
    float dx, dy;
    dx = px[0]-px[1]; dy = py[0]-py[1]; float ax1 = fast_sqrt(dx*dx + dy*dy);
    dx = px[1]-px[2]; dy = py[1]-py[2]; float ay1 = fast_sqrt(dx*dx + dy*dy);
    dx = px[2]-px[3]; dy = py[2]-py[3]; float ax2 = fast_sqrt(dx*dx + dy*dy);
    dx = px[3]-px[0]; dy = py[3]-py[0]; float ay2 = fast_sqrt(dx*dx + dy*dy);
    float sx = 0.25f * (ay1 + ay2);   // scale[...,0] = a_y/2 (multiplies x)
    float sy = 0.25f * (ax1 + ax2);   // scale[...,1] = a_x/2 (multiplies y)

    // centered floor points
    float fx[4], fy[4];
#pragma unroll
    for (int i = 0; i < 4; ++i) { fx[i] = px[i] - cx; fy[i] = py[i] - cy; }

    // Procrustes cross-covariance (sort-invariant); closed-form 2x2 Kabsch
    const float cubx[4] = {-1.f, -1.f,  1.f, 1.f};
    const float cuby[4] = { 1.f, -1.f, -1.f, 1.f};
    float Sxx = 0.f, Sxy = 0.f, Syx = 0.f, Syy = 0.f;
#pragma unroll
    for (int i = 0; i < 4; ++i) {
        Sxx += cubx[i] * fx[i];
        Sxy += cubx[i] * fy[i];
        Syx += cuby[i] * fx[i];
        Syy += cuby[i] * fy[i];
    }
    float rvar  = __fdividef(0.25f, sx*sx + sy*sy);
    float alpha = (sx * Sxx + sy * Syy) * rvar;   // scale_p * cos(theta)
    float beta  = (sx * Sxy - sy * Syx) * rvar;   // scale_p * sin(theta)

    // rectified points + pseudo-angle keys (monotonic with atan2(fx, fy+1e-12))
    float K[4], PX[4], PY[4];
#pragma unroll
    for (int i = 0; i < 4; ++i) {
        float wx = sx * cubx[i];
        float wy = sy * cuby[i];
        PX[i] = cx + alpha * wx - beta * wy;
        PY[i] = cy + beta  * wx + alpha * wy;
        float X = fx[i], Y = fy[i] + 1e-12f;
        float t = __fdividef(Y, fabsf(X) + fabsf(Y));
        K[i] = copysignf(1.f - t, X);
    }

    // parallel stable ranks: r_i = #{j<i: K_j <= K_i} + #{j>i: K_j < K_i}
    float K0=K[0], K1=K[1], K2=K[2], K3=K[3];
    int r0 = (int)(K1 <  K0) + (int)(K2 <  K0) + (int)(K3 < K0);
    int r1 = (int)(K0 <= K1) + (int)(K2 <  K1) + (int)(K3 < K1);
    int r2 = (int)(K0 <= K2) + (int)(K1 <= K2) + (int)(K3 < K2);
    int r3 = (int)(K0 <= K3) + (int)(K1 <= K3) + (int)(K2 <= K3);

    // select-based permutation: output slot s takes element whose rank == s
    float QX[4], QY[4];
#pragma unroll
    for (int s = 0; s < 4; ++s) {
        float qx = (r0 == s) ? PX[0] : (r1 == s) ? PX[1] : (r2 == s) ? PX[2] : PX[3];
        float qy = (r0 == s) ? PY[0] : (r1 == s) ? PY[1] : (r2 == s) ? PY[2] : PY[3];
        QX[s] = qx; QY[s] = qy;
    }

    float4* o_top = (float4*)(out + (size_t)b * 12);
    float4* o_bot = (float4*)(out + (size_t)B * 12 + (size_t)b * 12);
    o_top[0] = make_float4(QX[0], QY[0], ceil_z, QX[1]);
    o_top[1] = make_float4(QY[1], ceil_z, QX[2], QY[2]);
    o_top[2] = make_float4(ceil_z, QX[3], QY[3], ceil_z);
    o_bot[0] = make_float4(QX[0], QY[0], FLOOR_Z, QX[1]);
    o_bot[1] = make_float4(QY[1], FLOOR_Z, QX[2], QY[2]);
    o_bot[2] = make_float4(FLOOR_Z, QX[3], QY[3], FLOOR_Z);
}

extern "C" void kernel_launch(void* const* d_in, const int* in_sizes, int n_in,
                              void* d_out, int out_size)
{
    const float* top = (const float*)d_in[0];  // top_corners    [B,4,2]
    const float* bot = (const float*)d_in[1];  // bottom_corners [B,4,2]
    // d_in[2] = cuboid_axes (constant [[-1,1],[-1,-1],[1,-1],[1,1]], hardcoded)
    int B = in_sizes[0] / 8;
    int threads = 128;
    int blocks = (B + threads - 1) / threads;
    cuboid_align_kernel<<<blocks, threads>>>(top, bot, (float*)d_out, B);
}